// round 9
// baseline (speedup 1.0000x reference)
#include <cuda_runtime.h>
#include <math.h>
#include <stdint.h>

#define Bn 32
#define Ln 8192
#define Cn 64
#define Mn 64
#define Jn 128          // 2*Mn (cos/sin rows)
#define JG 192          // Jn + Cn
#define NCH 32          // stage-1 K chunks (K=256 each)

// ---- scratch (device globals; no allocation allowed) ----
__device__ float g_b1frag[8 * 1024 * 32 * 4];   // stage-1 A frags [mt][ks][lane][q]  (4MB)
__device__ float g_b3frag[64 * 8 * 16 * 32 * 4];// stage-3 A frags [lt][mt][ks][lane][q] (4MB)
__device__ float g_Aw[Mn * Cn * Cn];            // [k][i][o] = alpha_k * Wr
__device__ float g_Bw[Mn * Cn * Cn];            // [k][i][o] = alpha_k * Wi
__device__ float g_Pp[NCH * Bn * Jn * Cn];      // stage-1 partials [ch][b][j][c]
__device__ float g_G[Bn * JG * Cn];             // stage-3 B operand [b][j][o] (fp32)

// ---------------- helpers ----------------
__device__ __forceinline__ float totf32(float x) {
    uint32_t u;
    asm("cvt.rn.tf32.f32 %0, %1;" : "=r"(u) : "f"(x));
    return __uint_as_float(u);
}
__device__ __forceinline__ float4 totf32_4(float4 v) {
    v.x = totf32(v.x); v.y = totf32(v.y); v.z = totf32(v.z); v.w = totf32(v.w);
    return v;
}
__device__ __forceinline__ uint32_t fau(float x) { return __float_as_uint(x); }

// m16n8k8 tf32 mma: D(16x8 f32) += A(16x8 tf32, row) * B(8x8 tf32, col)
__device__ __forceinline__ void mma_t32(float c[4], const uint32_t a[4],
                                        uint32_t b0, uint32_t b1) {
    asm volatile(
        "mma.sync.aligned.m16n8k8.row.col.f32.tf32.tf32.f32 "
        "{%0,%1,%2,%3}, {%4,%5,%6,%7}, {%8,%9}, {%0,%1,%2,%3};"
        : "+f"(c[0]), "+f"(c[1]), "+f"(c[2]), "+f"(c[3])
        : "r"(a[0]), "r"(a[1]), "r"(a[2]), "r"(a[3]), "r"(b0), "r"(b1));
}

// ---------------------------------------------------------------------------
// Stage-1 A fragments: A[j][l], j = mt*16 + row, l = ks*8 + col.
// ---------------------------------------------------------------------------
__global__ void k_basis1() {
    int g = blockIdx.x * blockDim.x + threadIdx.x;   // 1M
    int q = g & 3, lane = (g >> 2) & 31, ks = (g >> 7) & 1023, mt = g >> 17;
    int j = mt * 16 + (lane >> 2) + (q & 1) * 8;
    int l = ks * 8 + (lane & 3) + ((q >> 1) & 1) * 4;
    int km = j >> 1;
    int m = (km * l) & (Ln - 1);                     // exact: < 2^19
    float th = (float)m * (6.2831853071795864769f / (float)Ln);
    float s, c; __sincosf(th, &s, &c);
    g_b1frag[g] = totf32((j & 1) ? s : c);
}

// Stage-3 A fragments: A[l][j], l = lt*128 + mt*16 + row, j = ks*8 + col.
__global__ void k_basis3() {
    int g = blockIdx.x * blockDim.x + threadIdx.x;   // 1M
    int q = g & 3, lane = (g >> 2) & 31, ks = (g >> 7) & 15;
    int mt = (g >> 11) & 7, lt = g >> 14;
    int l = lt * 128 + mt * 16 + (lane >> 2) + (q & 1) * 8;
    int j = ks * 8 + (lane & 3) + ((q >> 1) & 1) * 4;
    int km = j >> 1;
    int m = (km * l) & (Ln - 1);
    float th = (float)m * (6.2831853071795864769f / (float)Ln);
    float s, c; __sincosf(th, &s, &c);
    g_b3frag[g] = totf32((j & 1) ? s : c);
}

// ---------------------------------------------------------------------------
// Weight transpose [i][o][k] -> [k][i*64+o] with alpha folded; 32x32 smem tiles.
// ---------------------------------------------------------------------------
__global__ void k_prepW(const float* __restrict__ wr, const float* __restrict__ wi) {
    __shared__ float t0[32][33], t1[32][33];
    int tile = blockIdx.x;
    int rc0 = (tile >> 1) * 32, k0 = (tile & 1) * 32;
    int tx = threadIdx.x & 31, ty = threadIdx.x >> 5;
#pragma unroll
    for (int rr = ty; rr < 32; rr += 8) {
        t0[rr][tx] = wr[(rc0 + rr) * 64 + k0 + tx];
        t1[rr][tx] = wi[(rc0 + rr) * 64 + k0 + tx];
    }
    __syncthreads();
#pragma unroll
    for (int kk = ty; kk < 32; kk += 8) {
        int k = k0 + kk;
        float alpha = (k == 0 ? 1.0f : 2.0f) / (float)Ln;
        g_Aw[k * 4096 + rc0 + tx] = alpha * t0[tx][kk];
        g_Bw[k * 4096 + rc0 + tx] = alpha * t1[tx][kk];
    }
}

// ---------------------------------------------------------------------------
// Stage 1: P[j=128][c=64] = sum_l basis[j,l]*x[l,c]; K=256 per block.
// Warp grid 4(M) x 2(N): warp computes M=32 (2 m-tiles) x N=32 (4 n-tiles).
// Each B pair feeds 2 MMAs -> LDS per MMA halved vs 8x1 layout.
// ---------------------------------------------------------------------------
__global__ void __launch_bounds__(256) k_dft(const float* __restrict__ x) {
    int ch = blockIdx.x, b = blockIdx.y;
    __shared__ float Xs[2][32 * 72];                 // stride 72: conflict-free
    int t = threadIdx.x, w = t >> 5, lane = t & 31;
    int wm = w & 3, wn = w >> 2;
    int g = lane >> 2, tg = lane & 3;
    int row0 = t >> 4, c4 = t & 15;

    float c[2][4][4];
#pragma unroll
    for (int mt = 0; mt < 2; mt++)
#pragma unroll
        for (int nt = 0; nt < 4; nt++)
#pragma unroll
            for (int q = 0; q < 4; q++) c[mt][nt][q] = 0.0f;

    const float4* ap0 = (const float4*)g_b1frag +
                        ((size_t)(2 * wm * 1024 + ch * 32) * 32 + lane);
    const float4* ap1 = ap0 + (size_t)1024 * 32;
    const float* xb = x + (size_t)b * Ln * Cn + (size_t)ch * 256 * Cn;

    {
        float4 v0 = totf32_4(*(const float4*)&xb[row0 * Cn + c4 * 4]);
        float4 v1 = totf32_4(*(const float4*)&xb[(row0 + 16) * Cn + c4 * 4]);
        *(float4*)&Xs[0][row0 * 72 + c4 * 4] = v0;
        *(float4*)&Xs[0][(row0 + 16) * 72 + c4 * 4] = v1;
    }
    __syncthreads();

    for (int kc = 0; kc < 8; kc++) {
        int cur = kc & 1;
        float4 n0, n1;
        if (kc < 7) {                                // issue next-tile LDG early
            const float* xn = xb + (kc + 1) * 32 * Cn;
            n0 = *(const float4*)&xn[row0 * Cn + c4 * 4];
            n1 = *(const float4*)&xn[(row0 + 16) * Cn + c4 * 4];
        }
        float4 af0[4], af1[4];
#pragma unroll
        for (int s = 0; s < 4; s++) {
            af0[s] = ap0[(kc * 4 + s) * 32];
            af1[s] = ap1[(kc * 4 + s) * 32];
        }
#pragma unroll
        for (int ks4 = 0; ks4 < 4; ks4++) {
            uint32_t a0[4] = { fau(af0[ks4].x), fau(af0[ks4].y),
                               fau(af0[ks4].z), fau(af0[ks4].w) };
            uint32_t a1[4] = { fau(af1[ks4].x), fau(af1[ks4].y),
                               fau(af1[ks4].z), fau(af1[ks4].w) };
            int kr0 = ks4 * 8 + tg;
#pragma unroll
            for (int nt = 0; nt < 4; nt++) {
                int col = wn * 32 + nt * 8 + g;
                uint32_t b0 = fau(Xs[cur][kr0 * 72 + col]);
                uint32_t b1 = fau(Xs[cur][(kr0 + 4) * 72 + col]);
                mma_t32(c[0][nt], a0, b0, b1);
                mma_t32(c[1][nt], a1, b0, b1);
            }
        }
        if (kc < 7) {
            *(float4*)&Xs[cur ^ 1][row0 * 72 + c4 * 4] = totf32_4(n0);
            *(float4*)&Xs[cur ^ 1][(row0 + 16) * 72 + c4 * 4] = totf32_4(n1);
        }
        __syncthreads();
    }

#pragma unroll
    for (int mt = 0; mt < 2; mt++) {
        int j0 = wm * 32 + mt * 16 + g;
        float* dst = g_Pp + ((size_t)(ch * Bn + b) * Jn + j0) * Cn;
#pragma unroll
        for (int nt = 0; nt < 4; nt++) {
            int col = wn * 32 + nt * 8 + 2 * tg;
            *(float2*)&dst[col]          = make_float2(c[mt][nt][0], c[mt][nt][1]);
            *(float2*)&dst[8 * Cn + col] = make_float2(c[mt][nt][2], c[mt][nt][3]);
        }
    }
}

// ---------------------------------------------------------------------------
// Stage 2: fused partial-reduce + complex mix.  P0=XFr, P1=-XFi.
// ---------------------------------------------------------------------------
__global__ void k_mix() {
    int k = blockIdx.x, b = blockIdx.y, o = threadIdx.x;
    __shared__ float P0[Cn], P1[Cn];
    float p0 = 0.0f, p1 = 0.0f;
#pragma unroll 4
    for (int ch = 0; ch < NCH; ch++) {
        const float* src = g_Pp + ((size_t)(ch * Bn + b) * Jn + 2 * k) * Cn;
        p0 += src[o];
        p1 += src[Cn + o];
    }
    P0[o] = p0; P1[o] = p1;
    __syncthreads();
    float gr = 0.0f, gi = 0.0f;
#pragma unroll 8
    for (int i = 0; i < Cn; i++) {
        float a  = g_Aw[(k * Cn + i) * Cn + o];
        float bb = g_Bw[(k * Cn + i) * Cn + o];
        float pr = P0[i], pi = P1[i];
        gr += pr * a + pi * bb;
        gi += pi * a - pr * bb;
    }
    g_G[(b * JG + 2 * k) * Cn + o]     = gr;
    g_G[(b * JG + 2 * k + 1) * Cn + o] = gi;
}

__global__ void k_pwfill(const float* __restrict__ pw) {
    int b = blockIdx.x, t = threadIdx.x;
#pragma unroll
    for (int i = 0; i < 16; i++) {
        int idx = t + i * 256;
        int o = idx & 63, ic = idx >> 6;
        g_G[(b * JG + Jn + ic) * Cn + o] = pw[o * Cn + ic];
    }
}

// ---------------------------------------------------------------------------
// Stage 3: out[l=128][o=64] = sum_{j<192} bigA[l,j]*G[j,o] + bias.
// Warp grid 4(M) x 2(N); As stride 76 (conflict-free x-fragment LDS).
// ---------------------------------------------------------------------------
__global__ void __launch_bounds__(256) k_out(const float* __restrict__ x,
                                             const float* __restrict__ bias,
                                             float* __restrict__ out) {
    int lt = blockIdx.x, b = blockIdx.y;
    extern __shared__ __align__(16) float sm[];
    float* Gs = sm;                                  // [192][72]
    float* As = sm + 192 * 72;                       // [128][76]
    int t = threadIdx.x, w = t >> 5, lane = t & 31;
    int wm = w & 3, wn = w >> 2;
    int g = lane >> 2, tg = lane & 3;

    {                                                // stage G: 3072 float4
        const float4* src = (const float4*)(g_G + (size_t)b * JG * Cn);
#pragma unroll
        for (int i = 0; i < 12; i++) {
            int idx = t + i * 256;
            int j = idx >> 4, cc = idx & 15;
            *(float4*)&Gs[j * 72 + cc * 4] = totf32_4(src[idx]);
        }
        const float4* xs = (const float4*)(x + ((size_t)b * Ln + lt * 128) * Cn);
#pragma unroll
        for (int i = 0; i < 8; i++) {                // stage x: 2048 float4
            int idx = t + i * 256;
            int r = idx >> 4, cc = idx & 15;
            *(float4*)&As[r * 76 + cc * 4] = totf32_4(xs[idx]);
        }
    }
    __syncthreads();

    float c[2][4][4];
#pragma unroll
    for (int mt = 0; mt < 2; mt++)
#pragma unroll
        for (int nt = 0; nt < 4; nt++)
#pragma unroll
            for (int q = 0; q < 4; q++) c[mt][nt][q] = 0.0f;

    const float4* ap0 = (const float4*)g_b3frag +
                        ((size_t)((lt * 8 + 2 * wm) * 16) * 32 + lane);
    const float4* ap1 = ap0 + 16 * 32;
#pragma unroll
    for (int ks = 0; ks < 16; ks++) {                // basis part (K 0..127)
        float4 af0 = ap0[ks * 32];
        float4 af1 = ap1[ks * 32];
        uint32_t a0[4] = { fau(af0.x), fau(af0.y), fau(af0.z), fau(af0.w) };
        uint32_t a1[4] = { fau(af1.x), fau(af1.y), fau(af1.z), fau(af1.w) };
        int kr0 = ks * 8 + tg;
#pragma unroll
        for (int nt = 0; nt < 4; nt++) {
            int col = wn * 32 + nt * 8 + g;
            uint32_t b0 = fau(Gs[kr0 * 72 + col]);
            uint32_t b1 = fau(Gs[(kr0 + 4) * 72 + col]);
            mma_t32(c[0][nt], a0, b0, b1);
            mma_t32(c[1][nt], a1, b0, b1);
        }
    }
#pragma unroll
    for (int ks = 0; ks < 8; ks++) {                 // x part (K 128..191)
        int kk = ks * 8 + tg;
        uint32_t a0[4], a1[4];
        {
            int r0 = wm * 32 + g;
            a0[0] = fau(As[r0 * 76 + kk]);
            a0[1] = fau(As[(r0 + 8) * 76 + kk]);
            a0[2] = fau(As[r0 * 76 + kk + 4]);
            a0[3] = fau(As[(r0 + 8) * 76 + kk + 4]);
            int r1 = r0 + 16;
            a1[0] = fau(As[r1 * 76 + kk]);
            a1[1] = fau(As[(r1 + 8) * 76 + kk]);
            a1[2] = fau(As[r1 * 76 + kk + 4]);
            a1[3] = fau(As[(r1 + 8) * 76 + kk + 4]);
        }
        int kr0 = 128 + ks * 8 + tg;
#pragma unroll
        for (int nt = 0; nt < 4; nt++) {
            int col = wn * 32 + nt * 8 + g;
            uint32_t b0 = fau(Gs[kr0 * 72 + col]);
            uint32_t b1 = fau(Gs[(kr0 + 4) * 72 + col]);
            mma_t32(c[0][nt], a0, b0, b1);
            mma_t32(c[1][nt], a1, b0, b1);
        }
    }

#pragma unroll
    for (int mt = 0; mt < 2; mt++) {
        int l0 = lt * 128 + wm * 32 + mt * 16 + g;
        float* dst = out + ((size_t)b * Ln + l0) * Cn;
#pragma unroll
        for (int nt = 0; nt < 4; nt++) {
            int col = wn * 32 + nt * 8 + 2 * tg;
            float2 bb = *(const float2*)&bias[col];
            *(float2*)&dst[col] =
                make_float2(c[mt][nt][0] + bb.x, c[mt][nt][1] + bb.y);
            *(float2*)&dst[8 * Cn + col] =
                make_float2(c[mt][nt][2] + bb.x, c[mt][nt][3] + bb.y);
        }
    }
}

// ---------------------------------------------------------------------------
extern "C" void kernel_launch(void* const* d_in, const int* in_sizes, int n_in,
                              void* d_out, int out_size) {
    const float* x    = (const float*)d_in[0];
    const float* wr   = (const float*)d_in[1];
    const float* wi   = (const float*)d_in[2];
    const float* pw   = (const float*)d_in[3];
    const float* bias = (const float*)d_in[4];
    float* out = (float*)d_out;

    int smem3 = (192 * 72 + 128 * 76) * (int)sizeof(float);   // 94208 B
    cudaFuncSetAttribute(k_out, cudaFuncAttributeMaxDynamicSharedMemorySize, smem3);

    k_basis1<<<4096, 256>>>();
    k_basis3<<<4096, 256>>>();
    k_prepW<<<256, 256>>>(wr, wi);
    k_dft<<<dim3(NCH, Bn), 256>>>(x);
    k_mix<<<dim3(Mn, Bn), Cn>>>();
    k_pwfill<<<Bn, 256>>>(pw);
    k_out<<<dim3(Ln / 128, Bn), 256, smem3>>>(x, bias, out);
}

// round 10
// speedup vs baseline: 1.0273x; 1.0273x over previous
#include <cuda_runtime.h>
#include <math.h>
#include <stdint.h>

#define Bn 32
#define Ln 8192
#define Cn 64
#define Mn 64
#define Jn 128          // 2*Mn (cos/sin rows)
#define JG 192          // Jn + Cn
#define NCH 32          // stage-1 K chunks (K=256 each)

// ---- scratch (device globals; no allocation allowed) ----
__device__ float g_b1frag[8 * 1024 * 32 * 4];   // stage-1 A frags [mt][ks][lane][q]  (4MB)
__device__ float g_b3frag[64 * 8 * 16 * 32 * 4];// stage-3 A frags [lt][mt][ks][lane][q] (4MB)
__device__ float g_Aw[Mn * Cn * Cn];            // [k][i][o] = alpha_k * Wr
__device__ float g_Bw[Mn * Cn * Cn];            // [k][i][o] = alpha_k * Wi
__device__ float g_Pp[NCH * Bn * Jn * Cn];      // stage-1 partials [ch][b][j][c]
__device__ float g_G[Bn * JG * Cn];             // stage-3 B operand [b][j][o] (fp32)

// ---------------- helpers ----------------
__device__ __forceinline__ float totf32(float x) {
    uint32_t u;
    asm("cvt.rn.tf32.f32 %0, %1;" : "=r"(u) : "f"(x));
    return __uint_as_float(u);
}
__device__ __forceinline__ float4 totf32_4(float4 v) {
    v.x = totf32(v.x); v.y = totf32(v.y); v.z = totf32(v.z); v.w = totf32(v.w);
    return v;
}
__device__ __forceinline__ uint32_t fau(float x) { return __float_as_uint(x); }
__device__ __forceinline__ uint32_t ldg_tf32(const float* p) {
    uint32_t u;
    asm("cvt.rn.tf32.f32 %0, %1;" : "=r"(u) : "f"(__ldg(p)));
    return u;
}

// m16n8k8 tf32 mma: D(16x8 f32) += A(16x8 tf32, row) * B(8x8 tf32, col)
__device__ __forceinline__ void mma_t32(float c[4], const uint32_t a[4],
                                        uint32_t b0, uint32_t b1) {
    asm volatile(
        "mma.sync.aligned.m16n8k8.row.col.f32.tf32.tf32.f32 "
        "{%0,%1,%2,%3}, {%4,%5,%6,%7}, {%8,%9}, {%0,%1,%2,%3};"
        : "+f"(c[0]), "+f"(c[1]), "+f"(c[2]), "+f"(c[3])
        : "r"(a[0]), "r"(a[1]), "r"(a[2]), "r"(a[3]), "r"(b0), "r"(b1));
}

// ---------------------------------------------------------------------------
// Stage-1 A fragments: A[j][l], j = mt*16 + row, l = ks*8 + col.
// ---------------------------------------------------------------------------
__global__ void k_basis1() {
    int g = blockIdx.x * blockDim.x + threadIdx.x;   // 1M
    int q = g & 3, lane = (g >> 2) & 31, ks = (g >> 7) & 1023, mt = g >> 17;
    int j = mt * 16 + (lane >> 2) + (q & 1) * 8;
    int l = ks * 8 + (lane & 3) + ((q >> 1) & 1) * 4;
    int km = j >> 1;
    int m = (km * l) & (Ln - 1);                     // exact: < 2^19
    float th = (float)m * (6.2831853071795864769f / (float)Ln);
    float s, c; __sincosf(th, &s, &c);
    g_b1frag[g] = totf32((j & 1) ? s : c);
}

// Stage-3 A fragments: A[l][j], l = lt*128 + mt*16 + row, j = ks*8 + col.
__global__ void k_basis3() {
    int g = blockIdx.x * blockDim.x + threadIdx.x;   // 1M
    int q = g & 3, lane = (g >> 2) & 31, ks = (g >> 7) & 15;
    int mt = (g >> 11) & 7, lt = g >> 14;
    int l = lt * 128 + mt * 16 + (lane >> 2) + (q & 1) * 8;
    int j = ks * 8 + (lane & 3) + ((q >> 1) & 1) * 4;
    int km = j >> 1;
    int m = (km * l) & (Ln - 1);
    float th = (float)m * (6.2831853071795864769f / (float)Ln);
    float s, c; __sincosf(th, &s, &c);
    g_b3frag[g] = totf32((j & 1) ? s : c);
}

// ---------------------------------------------------------------------------
// Weight transpose [i][o][k] -> [k][i*64+o] with alpha folded; 32x32 smem tiles.
// ---------------------------------------------------------------------------
__global__ void k_prepW(const float* __restrict__ wr, const float* __restrict__ wi) {
    __shared__ float t0[32][33], t1[32][33];
    int tile = blockIdx.x;
    int rc0 = (tile >> 1) * 32, k0 = (tile & 1) * 32;
    int tx = threadIdx.x & 31, ty = threadIdx.x >> 5;
#pragma unroll
    for (int rr = ty; rr < 32; rr += 8) {
        t0[rr][tx] = wr[(rc0 + rr) * 64 + k0 + tx];
        t1[rr][tx] = wi[(rc0 + rr) * 64 + k0 + tx];
    }
    __syncthreads();
#pragma unroll
    for (int kk = ty; kk < 32; kk += 8) {
        int k = k0 + kk;
        float alpha = (k == 0 ? 1.0f : 2.0f) / (float)Ln;
        g_Aw[k * 4096 + rc0 + tx] = alpha * t0[tx][kk];
        g_Bw[k * 4096 + rc0 + tx] = alpha * t1[tx][kk];
    }
}

// ---------------------------------------------------------------------------
// Stage 1: P[j=128][c=64] = sum_l basis[j,l]*x[l,c]; K=256 per block.
// 8 warps; warp w owns j-strip [w*16, w*16+16).  Double-buffered x staging.
// (R8 version, unchanged — known 40us.)
// ---------------------------------------------------------------------------
__global__ void __launch_bounds__(256) k_dft(const float* __restrict__ x) {
    int ch = blockIdx.x, b = blockIdx.y;
    __shared__ float Xs[2][32 * 72];                 // stride 72: conflict-free
    int t = threadIdx.x, w = t >> 5, lane = t & 31;
    int g = lane >> 2, tg = lane & 3;
    int row0 = t >> 4, c4 = t & 15;

    float c[8][4];
#pragma unroll
    for (int nt = 0; nt < 8; nt++)
#pragma unroll
        for (int q = 0; q < 4; q++) c[nt][q] = 0.0f;

    const float4* ap = (const float4*)g_b1frag + ((size_t)(w * 1024 + ch * 32) * 32 + lane);
    const float* xb = x + (size_t)b * Ln * Cn + (size_t)ch * 256 * Cn;

    {
        float4 v0 = totf32_4(*(const float4*)&xb[row0 * Cn + c4 * 4]);
        float4 v1 = totf32_4(*(const float4*)&xb[(row0 + 16) * Cn + c4 * 4]);
        *(float4*)&Xs[0][row0 * 72 + c4 * 4] = v0;
        *(float4*)&Xs[0][(row0 + 16) * 72 + c4 * 4] = v1;
    }
    __syncthreads();

    for (int kc = 0; kc < 8; kc++) {
        int cur = kc & 1;
        float4 n0, n1;
        if (kc < 7) {                                // issue next-tile LDG early
            const float* xn = xb + (kc + 1) * 32 * Cn;
            n0 = *(const float4*)&xn[row0 * Cn + c4 * 4];
            n1 = *(const float4*)&xn[(row0 + 16) * Cn + c4 * 4];
        }
        float4 af[4];                                // prefetch A frags
#pragma unroll
        for (int s = 0; s < 4; s++) af[s] = ap[(kc * 4 + s) * 32];
#pragma unroll
        for (int ks4 = 0; ks4 < 4; ks4++) {
            uint32_t a[4] = { fau(af[ks4].x), fau(af[ks4].y),
                              fau(af[ks4].z), fau(af[ks4].w) };
            int kr0 = ks4 * 8 + tg;
#pragma unroll
            for (int nt = 0; nt < 8; nt++) {
                uint32_t b0 = fau(Xs[cur][kr0 * 72 + nt * 8 + g]);
                uint32_t b1 = fau(Xs[cur][(kr0 + 4) * 72 + nt * 8 + g]);
                mma_t32(c[nt], a, b0, b1);
            }
        }
        if (kc < 7) {
            *(float4*)&Xs[cur ^ 1][row0 * 72 + c4 * 4] = totf32_4(n0);
            *(float4*)&Xs[cur ^ 1][(row0 + 16) * 72 + c4 * 4] = totf32_4(n1);
        }
        __syncthreads();
    }

    float* dst = g_Pp + ((size_t)(ch * Bn + b) * Jn) * Cn;
    int j0 = w * 16 + g;
#pragma unroll
    for (int nt = 0; nt < 8; nt++) {
        *(float2*)&dst[j0 * Cn + nt * 8 + 2 * tg]       = make_float2(c[nt][0], c[nt][1]);
        *(float2*)&dst[(j0 + 8) * Cn + nt * 8 + 2 * tg] = make_float2(c[nt][2], c[nt][3]);
    }
}

// ---------------------------------------------------------------------------
// Stage 2: fused partial-reduce + complex mix.  P0=XFr, P1=-XFi.
// ---------------------------------------------------------------------------
__global__ void k_mix() {
    int k = blockIdx.x, b = blockIdx.y, o = threadIdx.x;
    __shared__ float P0[Cn], P1[Cn];
    float p0 = 0.0f, p1 = 0.0f;
#pragma unroll 4
    for (int ch = 0; ch < NCH; ch++) {
        const float* src = g_Pp + ((size_t)(ch * Bn + b) * Jn + 2 * k) * Cn;
        p0 += src[o];
        p1 += src[Cn + o];
    }
    P0[o] = p0; P1[o] = p1;
    __syncthreads();
    float gr = 0.0f, gi = 0.0f;
#pragma unroll 8
    for (int i = 0; i < Cn; i++) {
        float a  = g_Aw[(k * Cn + i) * Cn + o];
        float bb = g_Bw[(k * Cn + i) * Cn + o];
        float pr = P0[i], pi = P1[i];
        gr += pr * a + pi * bb;
        gi += pi * a - pr * bb;
    }
    g_G[(b * JG + 2 * k) * Cn + o]     = gr;
    g_G[(b * JG + 2 * k + 1) * Cn + o] = gi;
}

__global__ void k_pwfill(const float* __restrict__ pw) {
    int b = blockIdx.x, t = threadIdx.x;
#pragma unroll
    for (int i = 0; i < 16; i++) {
        int idx = t + i * 256;
        int o = idx & 63, ic = idx >> 6;
        g_G[(b * JG + Jn + ic) * Cn + o] = pw[o * Cn + ic];
    }
}

// ---------------------------------------------------------------------------
// Stage 3: out[l=128][o=64] = sum_{j<192} bigA[l,j]*G[j,o] + bias.
// ksteps 0..15: basis frags from global; 16..23: x A-fragments straight from
// global (no As smem buffer) -> smem 55.3KB -> 4 CTAs/SM (was 2).
// ---------------------------------------------------------------------------
__global__ void __launch_bounds__(256, 4) k_out(const float* __restrict__ x,
                                                const float* __restrict__ bias,
                                                float* __restrict__ out) {
    int lt = blockIdx.x, b = blockIdx.y;
    extern __shared__ __align__(16) float sm[];
    float* Gs = sm;                                  // [192][72]
    int t = threadIdx.x, w = t >> 5, lane = t & 31;
    int g = lane >> 2, tg = lane & 3;

    {                                                // stage G: 3072 float4
        const float4* src = (const float4*)(g_G + (size_t)b * JG * Cn);
#pragma unroll
        for (int i = 0; i < 12; i++) {
            int idx = t + i * 256;
            int j = idx >> 4, cc = idx & 15;
            *(float4*)&Gs[j * 72 + cc * 4] = totf32_4(src[idx]);
        }
    }
    __syncthreads();

    float c[8][4];
#pragma unroll
    for (int nt = 0; nt < 8; nt++)
#pragma unroll
        for (int q = 0; q < 4; q++) c[nt][q] = 0.0f;

    const float4* ap = (const float4*)g_b3frag + ((size_t)((lt * 8 + w) * 16) * 32 + lane);
#pragma unroll
    for (int ks = 0; ks < 16; ks++) {                // basis part (K 0..127)
        float4 af = ap[ks * 32];
        uint32_t a[4] = { fau(af.x), fau(af.y), fau(af.z), fau(af.w) };
        int kr0 = ks * 8 + tg;
#pragma unroll
        for (int nt = 0; nt < 8; nt++) {
            uint32_t b0 = fau(Gs[kr0 * 72 + nt * 8 + g]);
            uint32_t b1 = fau(Gs[(kr0 + 4) * 72 + nt * 8 + g]);
            mma_t32(c[nt], a, b0, b1);
        }
    }
    {                                                // x part (K 128..191)
        const float* xr = x + ((size_t)b * Ln + lt * 128 + w * 16 + g) * Cn;
#pragma unroll
        for (int ks = 0; ks < 8; ks++) {
            int kk = ks * 8 + tg;
            uint32_t a[4];
            a[0] = ldg_tf32(xr + kk);
            a[1] = ldg_tf32(xr + 8 * Cn + kk);
            a[2] = ldg_tf32(xr + kk + 4);
            a[3] = ldg_tf32(xr + 8 * Cn + kk + 4);
            int kr0 = 128 + ks * 8 + tg;
#pragma unroll
            for (int nt = 0; nt < 8; nt++) {
                uint32_t b0 = fau(Gs[kr0 * 72 + nt * 8 + g]);
                uint32_t b1 = fau(Gs[(kr0 + 4) * 72 + nt * 8 + g]);
                mma_t32(c[nt], a, b0, b1);
            }
        }
    }

    int l0 = lt * 128 + w * 16 + g;
#pragma unroll
    for (int nt = 0; nt < 8; nt++) {
        int col = nt * 8 + 2 * tg;
        float2 bb = *(const float2*)&bias[col];
        *(float2*)&out[((size_t)b * Ln + l0) * Cn + col] =
            make_float2(c[nt][0] + bb.x, c[nt][1] + bb.y);
        *(float2*)&out[((size_t)b * Ln + l0 + 8) * Cn + col] =
            make_float2(c[nt][2] + bb.x, c[nt][3] + bb.y);
    }
}

// ---------------------------------------------------------------------------
extern "C" void kernel_launch(void* const* d_in, const int* in_sizes, int n_in,
                              void* d_out, int out_size) {
    const float* x    = (const float*)d_in[0];
    const float* wr   = (const float*)d_in[1];
    const float* wi   = (const float*)d_in[2];
    const float* pw   = (const float*)d_in[3];
    const float* bias = (const float*)d_in[4];
    float* out = (float*)d_out;

    int smem3 = (192 * 72) * (int)sizeof(float);     // 55296 B -> 4 CTAs/SM
    cudaFuncSetAttribute(k_out, cudaFuncAttributeMaxDynamicSharedMemorySize, smem3);

    k_basis1<<<4096, 256>>>();
    k_basis3<<<4096, 256>>>();
    k_prepW<<<256, 256>>>(wr, wi);
    k_dft<<<dim3(NCH, Bn), 256>>>(x);
    k_mix<<<dim3(Mn, Bn), Cn>>>();
    k_pwfill<<<Bn, 256>>>(pw);
    k_out<<<dim3(Ln / 128, Bn), 256, smem3>>>(x, bias, out);
}

// round 11
// speedup vs baseline: 1.0626x; 1.0343x over previous
#include <cuda_runtime.h>
#include <math.h>
#include <stdint.h>

#define Bn 32
#define Ln 8192
#define Cn 64
#define Mn 64
#define Jn 128          // 2*Mn (cos/sin rows)
#define JG 192          // Jn + Cn
#define NCH 32          // stage-1 K chunks (K=256 each)

// ---- scratch (device globals; no allocation allowed) ----
__device__ float g_b1frag[8 * 1024 * 32 * 4];   // stage-1 A frags [mt][ks][lane][q]  (4MB)
__device__ float g_b3frag[64 * 8 * 16 * 32 * 4];// stage-3 A frags [lt][mt][ks][lane][q] (4MB)
__device__ float g_Aw[Mn * Cn * Cn];            // [k][i][o] = alpha_k * Wr
__device__ float g_Bw[Mn * Cn * Cn];            // [k][i][o] = alpha_k * Wi
__device__ float g_Pp[NCH * Bn * Jn * Cn];      // stage-1 partials [ch][b][j][c]
__device__ float g_G[Bn * JG * Cn];             // stage-3 B operand [b][j][o] (fp32)

// ---------------- helpers ----------------
__device__ __forceinline__ float totf32(float x) {
    uint32_t u;
    asm("cvt.rn.tf32.f32 %0, %1;" : "=r"(u) : "f"(x));
    return __uint_as_float(u);
}
__device__ __forceinline__ float4 totf32_4(float4 v) {
    v.x = totf32(v.x); v.y = totf32(v.y); v.z = totf32(v.z); v.w = totf32(v.w);
    return v;
}
__device__ __forceinline__ uint32_t fau(float x) { return __float_as_uint(x); }

// m16n8k8 tf32 mma: D(16x8 f32) += A(16x8 tf32, row) * B(8x8 tf32, col)
__device__ __forceinline__ void mma_t32(float c[4], const uint32_t a[4],
                                        uint32_t b0, uint32_t b1) {
    asm volatile(
        "mma.sync.aligned.m16n8k8.row.col.f32.tf32.tf32.f32 "
        "{%0,%1,%2,%3}, {%4,%5,%6,%7}, {%8,%9}, {%0,%1,%2,%3};"
        : "+f"(c[0]), "+f"(c[1]), "+f"(c[2]), "+f"(c[3])
        : "r"(a[0]), "r"(a[1]), "r"(a[2]), "r"(a[3]), "r"(b0), "r"(b1));
}

// ---------------------------------------------------------------------------
// Stage-1 A fragments: A[j][l], j = mt*16 + row, l = ks*8 + col.
// ---------------------------------------------------------------------------
__global__ void k_basis1() {
    int g = blockIdx.x * blockDim.x + threadIdx.x;   // 1M
    int q = g & 3, lane = (g >> 2) & 31, ks = (g >> 7) & 1023, mt = g >> 17;
    int j = mt * 16 + (lane >> 2) + (q & 1) * 8;
    int l = ks * 8 + (lane & 3) + ((q >> 1) & 1) * 4;
    int km = j >> 1;
    int m = (km * l) & (Ln - 1);                     // exact: < 2^19
    float th = (float)m * (6.2831853071795864769f / (float)Ln);
    float s, c; __sincosf(th, &s, &c);
    g_b1frag[g] = totf32((j & 1) ? s : c);
}

// Stage-3 A fragments: A[l][j], l = lt*128 + mt*16 + row, j = ks*8 + col.
__global__ void k_basis3() {
    int g = blockIdx.x * blockDim.x + threadIdx.x;   // 1M
    int q = g & 3, lane = (g >> 2) & 31, ks = (g >> 7) & 15;
    int mt = (g >> 11) & 7, lt = g >> 14;
    int l = lt * 128 + mt * 16 + (lane >> 2) + (q & 1) * 8;
    int j = ks * 8 + (lane & 3) + ((q >> 1) & 1) * 4;
    int km = j >> 1;
    int m = (km * l) & (Ln - 1);
    float th = (float)m * (6.2831853071795864769f / (float)Ln);
    float s, c; __sincosf(th, &s, &c);
    g_b3frag[g] = totf32((j & 1) ? s : c);
}

// ---------------------------------------------------------------------------
// Weight transpose [i][o][k] -> [k][i*64+o] with alpha folded; 32x32 smem tiles.
// ---------------------------------------------------------------------------
__global__ void k_prepW(const float* __restrict__ wr, const float* __restrict__ wi) {
    __shared__ float t0[32][33], t1[32][33];
    int tile = blockIdx.x;
    int rc0 = (tile >> 1) * 32, k0 = (tile & 1) * 32;
    int tx = threadIdx.x & 31, ty = threadIdx.x >> 5;
#pragma unroll
    for (int rr = ty; rr < 32; rr += 8) {
        t0[rr][tx] = wr[(rc0 + rr) * 64 + k0 + tx];
        t1[rr][tx] = wi[(rc0 + rr) * 64 + k0 + tx];
    }
    __syncthreads();
#pragma unroll
    for (int kk = ty; kk < 32; kk += 8) {
        int k = k0 + kk;
        float alpha = (k == 0 ? 1.0f : 2.0f) / (float)Ln;
        g_Aw[k * 4096 + rc0 + tx] = alpha * t0[tx][kk];
        g_Bw[k * 4096 + rc0 + tx] = alpha * t1[tx][kk];
    }
}

// ---------------------------------------------------------------------------
// Stage 1: P[j=128][c=64] = sum_l basis[j,l]*x[l,c]; K=256 per block.
// (R8 version, unchanged — known 40us.)
// ---------------------------------------------------------------------------
__global__ void __launch_bounds__(256) k_dft(const float* __restrict__ x) {
    int ch = blockIdx.x, b = blockIdx.y;
    __shared__ float Xs[2][32 * 72];                 // stride 72: conflict-free
    int t = threadIdx.x, w = t >> 5, lane = t & 31;
    int g = lane >> 2, tg = lane & 3;
    int row0 = t >> 4, c4 = t & 15;

    float c[8][4];
#pragma unroll
    for (int nt = 0; nt < 8; nt++)
#pragma unroll
        for (int q = 0; q < 4; q++) c[nt][q] = 0.0f;

    const float4* ap = (const float4*)g_b1frag + ((size_t)(w * 1024 + ch * 32) * 32 + lane);
    const float* xb = x + (size_t)b * Ln * Cn + (size_t)ch * 256 * Cn;

    {
        float4 v0 = totf32_4(*(const float4*)&xb[row0 * Cn + c4 * 4]);
        float4 v1 = totf32_4(*(const float4*)&xb[(row0 + 16) * Cn + c4 * 4]);
        *(float4*)&Xs[0][row0 * 72 + c4 * 4] = v0;
        *(float4*)&Xs[0][(row0 + 16) * 72 + c4 * 4] = v1;
    }
    __syncthreads();

    for (int kc = 0; kc < 8; kc++) {
        int cur = kc & 1;
        float4 n0, n1;
        if (kc < 7) {                                // issue next-tile LDG early
            const float* xn = xb + (kc + 1) * 32 * Cn;
            n0 = *(const float4*)&xn[row0 * Cn + c4 * 4];
            n1 = *(const float4*)&xn[(row0 + 16) * Cn + c4 * 4];
        }
        float4 af[4];                                // prefetch A frags
#pragma unroll
        for (int s = 0; s < 4; s++) af[s] = ap[(kc * 4 + s) * 32];
#pragma unroll
        for (int ks4 = 0; ks4 < 4; ks4++) {
            uint32_t a[4] = { fau(af[ks4].x), fau(af[ks4].y),
                              fau(af[ks4].z), fau(af[ks4].w) };
            int kr0 = ks4 * 8 + tg;
#pragma unroll
            for (int nt = 0; nt < 8; nt++) {
                uint32_t b0 = fau(Xs[cur][kr0 * 72 + nt * 8 + g]);
                uint32_t b1 = fau(Xs[cur][(kr0 + 4) * 72 + nt * 8 + g]);
                mma_t32(c[nt], a, b0, b1);
            }
        }
        if (kc < 7) {
            *(float4*)&Xs[cur ^ 1][row0 * 72 + c4 * 4] = totf32_4(n0);
            *(float4*)&Xs[cur ^ 1][(row0 + 16) * 72 + c4 * 4] = totf32_4(n1);
        }
        __syncthreads();
    }

    float* dst = g_Pp + ((size_t)(ch * Bn + b) * Jn) * Cn;
    int j0 = w * 16 + g;
#pragma unroll
    for (int nt = 0; nt < 8; nt++) {
        *(float2*)&dst[j0 * Cn + nt * 8 + 2 * tg]       = make_float2(c[nt][0], c[nt][1]);
        *(float2*)&dst[(j0 + 8) * Cn + nt * 8 + 2 * tg] = make_float2(c[nt][2], c[nt][3]);
    }
}

// ---------------------------------------------------------------------------
// Stage 2: fused partial-reduce + complex mix.  P0=XFr, P1=-XFi.
// ---------------------------------------------------------------------------
__global__ void k_mix() {
    int k = blockIdx.x, b = blockIdx.y, o = threadIdx.x;
    __shared__ float P0[Cn], P1[Cn];
    float p0 = 0.0f, p1 = 0.0f;
#pragma unroll 4
    for (int ch = 0; ch < NCH; ch++) {
        const float* src = g_Pp + ((size_t)(ch * Bn + b) * Jn + 2 * k) * Cn;
        p0 += src[o];
        p1 += src[Cn + o];
    }
    P0[o] = p0; P1[o] = p1;
    __syncthreads();
    float gr = 0.0f, gi = 0.0f;
#pragma unroll 8
    for (int i = 0; i < Cn; i++) {
        float a  = g_Aw[(k * Cn + i) * Cn + o];
        float bb = g_Bw[(k * Cn + i) * Cn + o];
        float pr = P0[i], pi = P1[i];
        gr += pr * a + pi * bb;
        gi += pi * a - pr * bb;
    }
    g_G[(b * JG + 2 * k) * Cn + o]     = gr;
    g_G[(b * JG + 2 * k + 1) * Cn + o] = gi;
}

__global__ void k_pwfill(const float* __restrict__ pw) {
    int b = blockIdx.x, t = threadIdx.x;
#pragma unroll
    for (int i = 0; i < 16; i++) {
        int idx = t + i * 256;
        int o = idx & 63, ic = idx >> 6;
        g_G[(b * JG + Jn + ic) * Cn + o] = pw[o * Cn + ic];
    }
}

// ---------------------------------------------------------------------------
// Stage 3: out[l=128][o=64] = sum_{j<192} bigA[l,j]*G[j,o] + bias.
// SMEM OVERLAY: As (128x72) reuses Gs rows 0..127 after the basis MMAs
// are done with them -> total smem 55.3KB -> 4 CTAs/SM, R8 access patterns.
// ---------------------------------------------------------------------------
__global__ void __launch_bounds__(256, 4) k_out(const float* __restrict__ x,
                                                const float* __restrict__ bias,
                                                float* __restrict__ out) {
    int lt = blockIdx.x, b = blockIdx.y;
    extern __shared__ __align__(16) float sm[];
    float* Gs = sm;                                  // [192][72]
    float* As = sm;                                  // overlay: rows 0..127 of Gs
    int t = threadIdx.x, w = t >> 5, lane = t & 31;
    int g = lane >> 2, tg = lane & 3;

    {                                                // stage G: 3072 float4
        const float4* src = (const float4*)(g_G + (size_t)b * JG * Cn);
#pragma unroll
        for (int i = 0; i < 12; i++) {
            int idx = t + i * 256;
            int j = idx >> 4, cc = idx & 15;
            *(float4*)&Gs[j * 72 + cc * 4] = totf32_4(src[idx]);
        }
    }
    __syncthreads();

    float c[8][4];
#pragma unroll
    for (int nt = 0; nt < 8; nt++)
#pragma unroll
        for (int q = 0; q < 4; q++) c[nt][q] = 0.0f;

    const float4* ap = (const float4*)g_b3frag + ((size_t)((lt * 8 + w) * 16) * 32 + lane);
#pragma unroll
    for (int ks = 0; ks < 16; ks++) {                // basis part (K 0..127)
        float4 af = ap[ks * 32];
        uint32_t a[4] = { fau(af.x), fau(af.y), fau(af.z), fau(af.w) };
        int kr0 = ks * 8 + tg;
#pragma unroll
        for (int nt = 0; nt < 8; nt++) {
            uint32_t b0 = fau(Gs[kr0 * 72 + nt * 8 + g]);
            uint32_t b1 = fau(Gs[(kr0 + 4) * 72 + nt * 8 + g]);
            mma_t32(c[nt], a, b0, b1);
        }
    }

    __syncthreads();                                 // Gs rows 0..127 now dead
    {                                                // stage x into overlay (coalesced)
        const float4* xs = (const float4*)(x + ((size_t)b * Ln + lt * 128) * Cn);
#pragma unroll
        for (int i = 0; i < 8; i++) {                // 2048 float4
            int idx = t + i * 256;
            int r = idx >> 4, cc = idx & 15;
            *(float4*)&As[r * 72 + cc * 4] = totf32_4(xs[idx]);
        }
    }
    __syncthreads();

#pragma unroll
    for (int ks = 0; ks < 8; ks++) {                 // x part (K 128..191)
        int kk = ks * 8 + tg;
        int r0 = w * 16 + g;
        uint32_t a[4];
        a[0] = fau(As[r0 * 72 + kk]);
        a[1] = fau(As[(r0 + 8) * 72 + kk]);
        a[2] = fau(As[r0 * 72 + kk + 4]);
        a[3] = fau(As[(r0 + 8) * 72 + kk + 4]);
        int kr0 = 128 + ks * 8 + tg;
#pragma unroll
        for (int nt = 0; nt < 8; nt++) {
            uint32_t b0 = fau(Gs[kr0 * 72 + nt * 8 + g]);
            uint32_t b1 = fau(Gs[(kr0 + 4) * 72 + nt * 8 + g]);
            mma_t32(c[nt], a, b0, b1);
        }
    }

    int l0 = lt * 128 + w * 16 + g;
#pragma unroll
    for (int nt = 0; nt < 8; nt++) {
        int col = nt * 8 + 2 * tg;
        float2 bb = *(const float2*)&bias[col];
        *(float2*)&out[((size_t)b * Ln + l0) * Cn + col] =
            make_float2(c[nt][0] + bb.x, c[nt][1] + bb.y);
        *(float2*)&out[((size_t)b * Ln + l0 + 8) * Cn + col] =
            make_float2(c[nt][2] + bb.x, c[nt][3] + bb.y);
    }
}

// ---------------------------------------------------------------------------
extern "C" void kernel_launch(void* const* d_in, const int* in_sizes, int n_in,
                              void* d_out, int out_size) {
    const float* x    = (const float*)d_in[0];
    const float* wr   = (const float*)d_in[1];
    const float* wi   = (const float*)d_in[2];
    const float* pw   = (const float*)d_in[3];
    const float* bias = (const float*)d_in[4];
    float* out = (float*)d_out;

    int smem3 = (JG * 72) * (int)sizeof(float);      // 55296 B -> 4 CTAs/SM
    cudaFuncSetAttribute(k_out, cudaFuncAttributeMaxDynamicSharedMemorySize, smem3);

    k_basis1<<<4096, 256>>>();
    k_basis3<<<4096, 256>>>();
    k_prepW<<<256, 256>>>(wr, wi);
    k_dft<<<dim3(NCH, Bn), 256>>>(x);
    k_mix<<<dim3(Mn, Bn), Cn>>>();
    k_pwfill<<<Bn, 256>>>(pw);
    k_out<<<dim3(Ln / 128, Bn), 256, smem3>>>(x, bias, out);
}

// round 12
// speedup vs baseline: 1.2314x; 1.1589x over previous
#include <cuda_runtime.h>
#include <math.h>
#include <stdint.h>

#define Bn 32
#define Ln 8192
#define Cn 64
#define Mn 64
#define Jn 128          // 2*Mn (cos/sin rows)
#define JG 192          // Jn + Cn
#define NCH 16          // stage-1 K chunks (K=512 each) -> 512 CTAs, single wave

// ---- scratch (device globals; no allocation allowed) ----
__device__ float g_b1frag[8 * 1024 * 32 * 4];   // stage-1 A frags [mt][ks][lane][q]  (4MB)
__device__ float g_b3frag[64 * 8 * 16 * 32 * 4];// stage-3 A frags [lt][mt][ks][lane][q] (4MB)
__device__ float g_Aw[Mn * Cn * Cn];            // [k][i][o] = alpha_k * Wr
__device__ float g_Bw[Mn * Cn * Cn];            // [k][i][o] = alpha_k * Wi
__device__ float g_Pp[NCH * Bn * Jn * Cn];      // stage-1 partials [ch][b][j][c]
__device__ float g_G[Bn * JG * Cn];             // stage-3 B operand [b][j][o] (fp32)

// ---------------- helpers ----------------
__device__ __forceinline__ float totf32(float x) {
    uint32_t u;
    asm("cvt.rn.tf32.f32 %0, %1;" : "=r"(u) : "f"(x));
    return __uint_as_float(u);
}
__device__ __forceinline__ float4 totf32_4(float4 v) {
    v.x = totf32(v.x); v.y = totf32(v.y); v.z = totf32(v.z); v.w = totf32(v.w);
    return v;
}
__device__ __forceinline__ uint32_t fau(float x) { return __float_as_uint(x); }

// m16n8k8 tf32 mma: D(16x8 f32) += A(16x8 tf32, row) * B(8x8 tf32, col)
__device__ __forceinline__ void mma_t32(float c[4], const uint32_t a[4],
                                        uint32_t b0, uint32_t b1) {
    asm volatile(
        "mma.sync.aligned.m16n8k8.row.col.f32.tf32.tf32.f32 "
        "{%0,%1,%2,%3}, {%4,%5,%6,%7}, {%8,%9}, {%0,%1,%2,%3};"
        : "+f"(c[0]), "+f"(c[1]), "+f"(c[2]), "+f"(c[3])
        : "r"(a[0]), "r"(a[1]), "r"(a[2]), "r"(a[3]), "r"(b0), "r"(b1));
}

// ---------------------------------------------------------------------------
// Merged prep: [0,4096) basis1, [4096,8192) basis3, [8192,8448) prepW,
// [8448,8480) pwfill.  All regions independent.
// ---------------------------------------------------------------------------
__global__ void __launch_bounds__(256) k_prep(const float* __restrict__ wr,
                                              const float* __restrict__ wi,
                                              const float* __restrict__ pw) {
    __shared__ float t0[32][33], t1[32][33];
    int bx = blockIdx.x;
    if (bx < 4096) {
        // Stage-1 A fragments: A[j][l], j = mt*16 + row, l = ks*8 + col.
        int g = bx * 256 + threadIdx.x;              // 1M
        int q = g & 3, lane = (g >> 2) & 31, ks = (g >> 7) & 1023, mt = g >> 17;
        int j = mt * 16 + (lane >> 2) + (q & 1) * 8;
        int l = ks * 8 + (lane & 3) + ((q >> 1) & 1) * 4;
        int m = ((j >> 1) * l) & (Ln - 1);           // exact: < 2^19
        float th = (float)m * (6.2831853071795864769f / (float)Ln);
        float s, c; __sincosf(th, &s, &c);
        g_b1frag[g] = totf32((j & 1) ? s : c);
    } else if (bx < 8192) {
        // Stage-3 A fragments: A[l][j], l = lt*128 + mt*16 + row, j = ks*8 + col.
        int g = (bx - 4096) * 256 + threadIdx.x;     // 1M
        int q = g & 3, lane = (g >> 2) & 31, ks = (g >> 7) & 15;
        int mt = (g >> 11) & 7, lt = g >> 14;
        int l = lt * 128 + mt * 16 + (lane >> 2) + (q & 1) * 8;
        int j = ks * 8 + (lane & 3) + ((q >> 1) & 1) * 4;
        int m = ((j >> 1) * l) & (Ln - 1);
        float th = (float)m * (6.2831853071795864769f / (float)Ln);
        float s, c; __sincosf(th, &s, &c);
        g_b3frag[g] = totf32((j & 1) ? s : c);
    } else if (bx < 8448) {
        // Weight transpose [i][o][k] -> [k][i*64+o] with alpha folded.
        int tile = bx - 8192;
        int rc0 = (tile >> 1) * 32, k0 = (tile & 1) * 32;
        int tx = threadIdx.x & 31, ty = threadIdx.x >> 5;
#pragma unroll
        for (int rr = ty; rr < 32; rr += 8) {
            t0[rr][tx] = wr[(rc0 + rr) * 64 + k0 + tx];
            t1[rr][tx] = wi[(rc0 + rr) * 64 + k0 + tx];
        }
        __syncthreads();
#pragma unroll
        for (int kk = ty; kk < 32; kk += 8) {
            int k = k0 + kk;
            float alpha = (k == 0 ? 1.0f : 2.0f) / (float)Ln;
            g_Aw[k * 4096 + rc0 + tx] = alpha * t0[tx][kk];
            g_Bw[k * 4096 + rc0 + tx] = alpha * t1[tx][kk];
        }
    } else {
        // pw rows of G (rows 128..191), per batch.
        int b = bx - 8448, t = threadIdx.x;
#pragma unroll
        for (int i = 0; i < 16; i++) {
            int idx = t + i * 256;
            int o = idx & 63, ic = idx >> 6;
            g_G[(b * JG + Jn + ic) * Cn + o] = pw[o * Cn + ic];
        }
    }
}

// ---------------------------------------------------------------------------
// Stage 1: P[j=128][c=64] = sum_l basis[j,l]*x[l,c]; K=512 per block.
// 8 warps; warp w owns j-strip [w*16, w*16+16).  Double-buffered x staging.
// (R8 inner loop, 16 kc iterations.)
// ---------------------------------------------------------------------------
__global__ void __launch_bounds__(256) k_dft(const float* __restrict__ x) {
    int ch = blockIdx.x, b = blockIdx.y;
    __shared__ float Xs[2][32 * 72];                 // stride 72: conflict-free
    int t = threadIdx.x, w = t >> 5, lane = t & 31;
    int g = lane >> 2, tg = lane & 3;
    int row0 = t >> 4, c4 = t & 15;

    float c[8][4];
#pragma unroll
    for (int nt = 0; nt < 8; nt++)
#pragma unroll
        for (int q = 0; q < 4; q++) c[nt][q] = 0.0f;

    const float4* ap = (const float4*)g_b1frag + ((size_t)(w * 1024 + ch * 64) * 32 + lane);
    const float* xb = x + (size_t)b * Ln * Cn + (size_t)ch * 512 * Cn;

    {
        float4 v0 = totf32_4(*(const float4*)&xb[row0 * Cn + c4 * 4]);
        float4 v1 = totf32_4(*(const float4*)&xb[(row0 + 16) * Cn + c4 * 4]);
        *(float4*)&Xs[0][row0 * 72 + c4 * 4] = v0;
        *(float4*)&Xs[0][(row0 + 16) * 72 + c4 * 4] = v1;
    }
    __syncthreads();

    for (int kc = 0; kc < 16; kc++) {
        int cur = kc & 1;
        float4 n0, n1;
        if (kc < 15) {                               // issue next-tile LDG early
            const float* xn = xb + (kc + 1) * 32 * Cn;
            n0 = *(const float4*)&xn[row0 * Cn + c4 * 4];
            n1 = *(const float4*)&xn[(row0 + 16) * Cn + c4 * 4];
        }
        float4 af[4];                                // prefetch A frags
#pragma unroll
        for (int s = 0; s < 4; s++) af[s] = ap[(kc * 4 + s) * 32];
#pragma unroll
        for (int ks4 = 0; ks4 < 4; ks4++) {
            uint32_t a[4] = { fau(af[ks4].x), fau(af[ks4].y),
                              fau(af[ks4].z), fau(af[ks4].w) };
            int kr0 = ks4 * 8 + tg;
#pragma unroll
            for (int nt = 0; nt < 8; nt++) {
                uint32_t b0 = fau(Xs[cur][kr0 * 72 + nt * 8 + g]);
                uint32_t b1 = fau(Xs[cur][(kr0 + 4) * 72 + nt * 8 + g]);
                mma_t32(c[nt], a, b0, b1);
            }
        }
        if (kc < 15) {
            *(float4*)&Xs[cur ^ 1][row0 * 72 + c4 * 4] = totf32_4(n0);
            *(float4*)&Xs[cur ^ 1][(row0 + 16) * 72 + c4 * 4] = totf32_4(n1);
        }
        __syncthreads();
    }

    float* dst = g_Pp + ((size_t)(ch * Bn + b) * Jn) * Cn;
    int j0 = w * 16 + g;
#pragma unroll
    for (int nt = 0; nt < 8; nt++) {
        *(float2*)&dst[j0 * Cn + nt * 8 + 2 * tg]       = make_float2(c[nt][0], c[nt][1]);
        *(float2*)&dst[(j0 + 8) * Cn + nt * 8 + 2 * tg] = make_float2(c[nt][2], c[nt][3]);
    }
}

// ---------------------------------------------------------------------------
// Stage 2: fused partial-reduce + complex mix.  P0=XFr, P1=-XFi.
// ---------------------------------------------------------------------------
__global__ void k_mix() {
    int k = blockIdx.x, b = blockIdx.y, o = threadIdx.x;
    __shared__ float P0[Cn], P1[Cn];
    float p0 = 0.0f, p1 = 0.0f;
#pragma unroll 4
    for (int ch = 0; ch < NCH; ch++) {
        const float* src = g_Pp + ((size_t)(ch * Bn + b) * Jn + 2 * k) * Cn;
        p0 += src[o];
        p1 += src[Cn + o];
    }
    P0[o] = p0; P1[o] = p1;
    __syncthreads();
    float gr = 0.0f, gi = 0.0f;
#pragma unroll 8
    for (int i = 0; i < Cn; i++) {
        float a  = g_Aw[(k * Cn + i) * Cn + o];
        float bb = g_Bw[(k * Cn + i) * Cn + o];
        float pr = P0[i], pi = P1[i];
        gr += pr * a + pi * bb;
        gi += pi * a - pr * bb;
    }
    g_G[(b * JG + 2 * k) * Cn + o]     = gr;
    g_G[(b * JG + 2 * k + 1) * Cn + o] = gi;
}

// ---------------------------------------------------------------------------
// Stage 3: out[l=128][o=64] = sum_{j<192} bigA[l,j]*G[j,o] + bias.
// (R8 version, unchanged — best known.)
// ---------------------------------------------------------------------------
__global__ void __launch_bounds__(256) k_out(const float* __restrict__ x,
                                             const float* __restrict__ bias,
                                             float* __restrict__ out) {
    int lt = blockIdx.x, b = blockIdx.y;
    extern __shared__ __align__(16) float sm[];
    float* Gs = sm;                                  // [192][72]
    float* As = sm + 192 * 72;                       // [128][72]
    int t = threadIdx.x, w = t >> 5, lane = t & 31;
    int g = lane >> 2, tg = lane & 3;

    {                                                // stage G: 3072 float4
        const float4* src = (const float4*)(g_G + (size_t)b * JG * Cn);
#pragma unroll
        for (int i = 0; i < 12; i++) {
            int idx = t + i * 256;
            int j = idx >> 4, cc = idx & 15;
            *(float4*)&Gs[j * 72 + cc * 4] = totf32_4(src[idx]);
        }
        const float4* xs = (const float4*)(x + ((size_t)b * Ln + lt * 128) * Cn);
#pragma unroll
        for (int i = 0; i < 8; i++) {                // stage x: 2048 float4
            int idx = t + i * 256;
            int r = idx >> 4, cc = idx & 15;
            *(float4*)&As[r * 72 + cc * 4] = totf32_4(xs[idx]);
        }
    }
    __syncthreads();

    float c[8][4];
#pragma unroll
    for (int nt = 0; nt < 8; nt++)
#pragma unroll
        for (int q = 0; q < 4; q++) c[nt][q] = 0.0f;

    const float4* ap = (const float4*)g_b3frag + ((size_t)((lt * 8 + w) * 16) * 32 + lane);
#pragma unroll
    for (int ks = 0; ks < 16; ks++) {                // basis part (K 0..127)
        float4 af = ap[ks * 32];
        uint32_t a[4] = { fau(af.x), fau(af.y), fau(af.z), fau(af.w) };
        int kr0 = ks * 8 + tg;
#pragma unroll
        for (int nt = 0; nt < 8; nt++) {
            uint32_t b0 = fau(Gs[kr0 * 72 + nt * 8 + g]);
            uint32_t b1 = fau(Gs[(kr0 + 4) * 72 + nt * 8 + g]);
            mma_t32(c[nt], a, b0, b1);
        }
    }
#pragma unroll
    for (int ks = 0; ks < 8; ks++) {                 // x part (K 128..191)
        int kk = ks * 8 + tg;
        int r0 = w * 16 + g;
        uint32_t a[4];
        a[0] = fau(As[r0 * 72 + kk]);
        a[1] = fau(As[(r0 + 8) * 72 + kk]);
        a[2] = fau(As[r0 * 72 + kk + 4]);
        a[3] = fau(As[(r0 + 8) * 72 + kk + 4]);
        int kr0 = 128 + ks * 8 + tg;
#pragma unroll
        for (int nt = 0; nt < 8; nt++) {
            uint32_t b0 = fau(Gs[kr0 * 72 + nt * 8 + g]);
            uint32_t b1 = fau(Gs[(kr0 + 4) * 72 + nt * 8 + g]);
            mma_t32(c[nt], a, b0, b1);
        }
    }

    int l0 = lt * 128 + w * 16 + g;
#pragma unroll
    for (int nt = 0; nt < 8; nt++) {
        int col = nt * 8 + 2 * tg;
        float2 bb = *(const float2*)&bias[col];
        *(float2*)&out[((size_t)b * Ln + l0) * Cn + col] =
            make_float2(c[nt][0] + bb.x, c[nt][1] + bb.y);
        *(float2*)&out[((size_t)b * Ln + l0 + 8) * Cn + col] =
            make_float2(c[nt][2] + bb.x, c[nt][3] + bb.y);
    }
}

// ---------------------------------------------------------------------------
extern "C" void kernel_launch(void* const* d_in, const int* in_sizes, int n_in,
                              void* d_out, int out_size) {
    const float* x    = (const float*)d_in[0];
    const float* wr   = (const float*)d_in[1];
    const float* wi   = (const float*)d_in[2];
    const float* pw   = (const float*)d_in[3];
    const float* bias = (const float*)d_in[4];
    float* out = (float*)d_out;

    int smem3 = (192 * 72 + 128 * 72) * (int)sizeof(float);   // 92160 B
    cudaFuncSetAttribute(k_out, cudaFuncAttributeMaxDynamicSharedMemorySize, smem3);

    k_prep<<<8480, 256>>>(wr, wi, pw);
    k_dft<<<dim3(NCH, Bn), 256>>>(x);
    k_mix<<<dim3(Mn, Bn), Cn>>>();
    k_out<<<dim3(Ln / 128, Bn), 256, smem3>>>(x, bias, out);
}